// round 16
// baseline (speedup 1.0000x reference)
#include <cuda_runtime.h>
#include <cstdint>

// ------------------------- problem dims -------------------------
#define B_ 32
#define T_ 100
#define V_ 20000
#define E_ 128
#define H_ 128
#define M_ 64
#define ROWS_X (B_*T_)          // 3200
#define ROWS_TOT (ROWS_X + B_)  // 3232

// ------------------------- k1 config ----------------------------
#define CK 64                   // k per chunk (64 fp16 = 128B rows, SW128)
#define NCH 313                 // ceil(20000/64)
#define NRT 13                  // row tiles of 256 (3328 rows padded)
#define NSPL 34                 // K splits
#define BASECH 9                // 313 = 7*10 + 27*9
#define EXTRA 7
#define GRID1 (NRT*NSPL)        // 442  (2.99 waves at 1 CTA/SM)

// per-stage smem: AH 32K | BH 16K = 48KB; 3 stages = 144KB
#define STG_BYTES 49152
#define OFF_AH 0
#define OFF_BH 32768
#define SMEM_K1 (3*STG_BYTES)

// k3 dynamic smem layout (floats)
#define K3_XP   0                    // [100*384]
#define K3_RP   (K3_XP + T_*384)     // [384] (only 128..383 used)
#define K3_H    (K3_RP + 384)        // [128]
#define K3_MSK  (K3_H + 128)         // [100]
#define K3_CS   (K3_MSK + 100)       // [64]
#define SMEM_K3 ((K3_CS + 64 + 4) * 4)   // ~156.4 KB

// ------------------------- scratch globals ----------------------
__device__ float    g_acc[(size_t)ROWS_TOT * 128];   // 1.65 MB, L2-resident
__device__ uint32_t g_ebh[(size_t)NCH * 4096];       // emb fp16, tile-swizzled
__device__ float    g_gkT[384 * 128];                // gru_k transposed [j][k]
__device__ float    g_P[(size_t)ROWS_X * 384];
__device__ float    g_mask[ROWS_X];
__device__ float    g_ae[B_ * E_];

// ------------------------- helpers ------------------------------
__device__ __forceinline__ unsigned su32(const void* p) {
    return (unsigned)__cvta_generic_to_shared(p);
}
__device__ __forceinline__ void cpa16(unsigned dst, const void* src) {
    asm volatile("cp.async.ca.shared.global [%0], [%1], 16;\n"
                 :: "r"(dst), "l"(src));
}
__device__ __forceinline__ void ldsm4(uint32_t* r, uint32_t addr) {
    asm volatile("ldmatrix.sync.aligned.m8n8.x4.shared.b16 {%0,%1,%2,%3}, [%4];"
                 : "=r"(r[0]), "=r"(r[1]), "=r"(r[2]), "=r"(r[3]) : "r"(addr));
}
__device__ __forceinline__ void mma16816(float* c, const uint32_t* a, const uint32_t* b) {
    asm volatile("mma.sync.aligned.m16n8k16.row.col.f32.f16.f16.f32 "
                 "{%0,%1,%2,%3}, {%4,%5,%6,%7}, {%8,%9}, {%0,%1,%2,%3};"
                 : "+f"(c[0]), "+f"(c[1]), "+f"(c[2]), "+f"(c[3])
                 : "r"(a[0]), "r"(a[1]), "r"(a[2]), "r"(a[3]), "r"(b[0]), "r"(b[1]));
}
// pack two floats -> fp16x2
__device__ __forceinline__ void cvt2h(float a, float b, uint32_t& p) {
    asm("cvt.rn.f16x2.f32 %0, %1, %2;" : "=r"(p) : "f"(b), "f"(a));
}
__device__ __forceinline__ void redadd(float* p, float v) {
    asm volatile("red.global.add.f32 [%0], %1;" :: "l"(p), "f"(v) : "memory");
}

// fast transcendentals (MUFU-based, err ~2^-22)
#define LOG2E_ 1.4426950408889634f
__device__ __forceinline__ float ex2f(float x) {
    float r; asm("ex2.approx.f32 %0, %1;" : "=f"(r) : "f"(x)); return r;
}
__device__ __forceinline__ float rcpf(float x) {
    float r; asm("rcp.approx.f32 %0, %1;" : "=f"(r) : "f"(x)); return r;
}
__device__ __forceinline__ float sigmoid_f(float v) {
    return rcpf(1.f + ex2f(-v * LOG2E_));
}
__device__ __forceinline__ float tanh_f(float v) {
    return 1.f - 2.f * rcpf(ex2f(2.f * LOG2E_ * v) + 1.f);
}

// ---------------------------------------------------------------------------
// Kernel z: zero the accumulator.
// ---------------------------------------------------------------------------
__global__ void __launch_bounds__(256) kz_zero()
{
    int i = blockIdx.x * 256 + threadIdx.x;
    reinterpret_cast<float4*>(g_acc)[i] = make_float4(0.f, 0.f, 0.f, 0.f);
}

// ---------------------------------------------------------------------------
// Kernel 0: emb -> transposed fp16, SW128-swizzled 16KB tiles.
// ---------------------------------------------------------------------------
__global__ void __launch_bounds__(256) k0_prep(const float* __restrict__ emb)
{
    __shared__ float se[64][129];   // [kl][n]
    const int c = blockIdx.x, tid = threadIdx.x;

    for (int i = tid; i < 64 * 128; i += 256) {
        int kl = i >> 7, r = i & 127;
        int k = c * CK + kl;
        se[kl][r] = (k < V_) ? emb[(size_t)k * E_ + r] : 0.f;
    }
    __syncthreads();

    uint32_t* oh = g_ebh + (size_t)c * 4096;
    for (int p = tid; p < 4096; p += 256) {
        uint32_t bo = p * 4;
        uint32_t lg = bo ^ ((bo >> 3) & 0x70);   // swizzle is an involution
        int r = lg >> 7, kl0 = (lg & 127) >> 1;
        uint32_t hw;
        cvt2h(se[kl0][r], se[kl0 + 1][r], hw);
        oh[p] = hw;
    }
}

// ---------------------------------------------------------------------------
// Kernel 0b: transpose gru_k -> gkT[j][k].
// ---------------------------------------------------------------------------
__global__ void __launch_bounds__(128) k0b_gkT(const float* __restrict__ gk)
{
    const int j = blockIdx.x;       // 0..383
    const int k = threadIdx.x;      // 0..127
    g_gkT[j * 128 + k] = gk[k * 384 + j];
}

// ---------------------------------------------------------------------------
// Kernel 1 (v2): 1-term fp16 GEMM, CTA tile 256x128, 256 threads, 8 warps in
// 4(M)x2(N) grid of 64x64 warp tiles -> 0.25 ldsm/mma (half the L1 traffic).
// 3-stage pipeline, wait_group 1; atomic split-K reduction into g_acc.
// ---------------------------------------------------------------------------
__global__ void __launch_bounds__(256, 1) k1_gemm(
    const float* __restrict__ x, const float* __restrict__ a_)
{
    extern __shared__ char smem[];
    const uint32_t sb = su32(smem);
    const int tid = threadIdx.x;
    const int lane = tid & 31;
    const int wid = tid >> 5;
    const int wm = wid >> 1;            // 0..3 (M quarters of 64)
    const int wn = wid & 1;             // 0..1 (N halves of 64)

    const int rt = blockIdx.x % NRT;
    const int sp = blockIdx.x / NRT;
    const int m0 = rt * 256;
    const int nch = BASECH + (sp < EXTRA ? 1 : 0);
    const int c0  = sp * BASECH + (sp < EXTRA ? sp : EXTRA);

    // ---- A loader: 1 thread per row, 64 floats in 2 waves of 32 ----
    const int arow = tid;               // 0..255
    const uint32_t xs_a = (uint32_t)(arow & 7) << 4;

    const float* rowp;
    {
        int m = m0 + arow;
        if (m < ROWS_X)        rowp = x  + (size_t)m * V_;
        else if (m < ROWS_TOT) rowp = a_ + (size_t)(m - ROWS_X) * V_;
        else                   rowp = nullptr;
    }

    // ---- ldmatrix per-lane constants ----
    const int aq = lane >> 3;
    const int a_row_off = (aq & 1) * 8 + (lane & 7);
    const uint32_t a_kboff = (uint32_t)(aq >> 1) * 16;
    const int bjj = lane >> 4;
    const uint32_t b_kboff = (uint32_t)((lane >> 3) & 1) * 16;
    const uint32_t xorv = (uint32_t)(lane & 7) << 4;
    uint32_t abase[4], bbase[4];
    #pragma unroll
    for (int i = 0; i < 4; i++)
        abase[i] = (uint32_t)(wm * 64 + i * 16 + a_row_off) * 128;
    #pragma unroll
    for (int j = 0; j < 4; j++)
        bbase[j] = (uint32_t)(wn * 64 + j * 16 + bjj * 8 + (lane & 7)) * 128;

    float acc[4][8][4];   // [m16-frag][n8-frag][reg]
    #pragma unroll
    for (int i = 0; i < 4; i++)
        #pragma unroll
        for (int j = 0; j < 8; j++)
            #pragma unroll
            for (int q = 0; q < 4; q++) acc[i][j][q] = 0.f;

    float4 av[8];   // one 32-float wave

    // wave w of chunk c: floats k = w*32 + q*4
    auto loadA = [&](int c, int w) {
        #pragma unroll
        for (int q = 0; q < 8; q++) {
            int kb = c * CK + w * 32 + q * 4;
            av[q] = (rowp && kb < V_) ? *(const float4*)(rowp + kb)
                                      : make_float4(0.f, 0.f, 0.f, 0.f);
        }
    };
    auto stsA = [&](int s, int w) {
        const uint32_t ah = sb + s * STG_BYTES + OFF_AH + arow * 128;
        #pragma unroll
        for (int q = 0; q < 8; q++) {
            uint32_t ina = ((uint32_t)(w * 64 + q * 8)) ^ xs_a;
            float4 v = av[q];
            uint32_t h0, h1;
            cvt2h(v.x, v.y, h0);
            cvt2h(v.z, v.w, h1);
            asm volatile("st.shared.v2.b32 [%0], {%1,%2};" :: "r"(ah + ina), "r"(h0), "r"(h1));
        }
    };
    auto cpB = [&](int c, int s) {
        const char* srcH = (const char*)g_ebh + (size_t)c * 16384;
        const uint32_t bh = sb + s * STG_BYTES + OFF_BH;
        #pragma unroll
        for (int j = 0; j < 4; j++) {
            int off = (j * 256 + tid) * 16;
            cpa16(bh + off, srcH + off);
        }
        asm volatile("cp.async.commit_group;");
    };

    auto mmaStep = [&](int s, int ks) {
        const uint32_t ahs = sb + s * STG_BYTES + OFF_AH;
        const uint32_t bhs = sb + s * STG_BYTES + OFF_BH;
        const uint32_t kta = ((uint32_t)(ks * 32) + a_kboff) ^ xorv;
        const uint32_t ktb = ((uint32_t)(ks * 32) + b_kboff) ^ xorv;
        uint32_t ah[4][4], bh[4][4];
        #pragma unroll
        for (int i = 0; i < 4; i++) ldsm4(ah[i], ahs + abase[i] + kta);
        #pragma unroll
        for (int j = 0; j < 4; j++) ldsm4(bh[j], bhs + bbase[j] + ktb);
        #pragma unroll
        for (int i = 0; i < 4; i++) {
            #pragma unroll
            for (int j = 0; j < 8; j++) {
                const uint32_t* bhp = &bh[j >> 1][(j & 1) * 2];
                mma16816(acc[i][j], ah[i], bhp);
            }
        }
    };

    // ---- prologue: stage0 fully; B of stage1; A wave0 of chunk1 in regs ----
    loadA(c0, 0); stsA(0, 0);
    loadA(c0, 1); stsA(0, 1);
    cpB(c0, 0);
    if (nch > 1) { loadA(c0 + 1, 0); cpB(c0 + 1, 1); }

    for (int t = 0; t < nch; t++) {
        const int s = t % 3;
        if (t >= nch - 2) {
            asm volatile("cp.async.wait_group 0;" ::: "memory");
        } else {
            asm volatile("cp.async.wait_group 1;" ::: "memory");
        }
        __syncthreads();   // stage s ready; stage (t+1)%3 free of readers

        if (t + 1 < nch) stsA((t + 1) % 3, 0);   // av holds chunk t+1 wave0
        mmaStep(s, 0);
        mmaStep(s, 1);
        if (t + 1 < nch) loadA(c0 + t + 1, 1);
        mmaStep(s, 2);
        if (t + 1 < nch) stsA((t + 1) % 3, 1);
        mmaStep(s, 3);
        if (t + 2 < nch) { loadA(c0 + t + 2, 0); cpB(c0 + t + 2, (t + 2) % 3); }
    }

    // ---- epilogue: atomically accumulate this split's tile ----
    const int gid = lane >> 2, tig = lane & 3;
    #pragma unroll
    for (int i = 0; i < 4; i++) {
        int mrow = m0 + wm * 64 + i * 16 + gid;
        #pragma unroll
        for (int j = 0; j < 8; j++) {
            int n = wn * 64 + j * 8 + tig * 2;
            if (mrow < ROWS_TOT) {
                float* d0 = g_acc + (size_t)mrow * 128 + n;
                redadd(d0,     acc[i][j][0]);
                redadd(d0 + 1, acc[i][j][1]);
            }
            if (mrow + 8 < ROWS_TOT) {
                float* d1 = g_acc + (size_t)(mrow + 8) * 128 + n;
                redadd(d1,     acc[i][j][2]);
                redadd(d1 + 1, acc[i][j][3]);
            }
        }
    }
}

// ---------------------------------------------------------------------------
// Kernel 2: tanh(g_acc) -> xe; mask; x_proj = xe@gkT + b_i.
// ---------------------------------------------------------------------------
__global__ void __launch_bounds__(384) k2_reduce_proj(const float* __restrict__ gbi)
{
    __shared__ float xs[8][128];
    __shared__ int nz[8];
    const int tid = threadIdx.x;
    const int r0 = blockIdx.x * 8;

    if (tid < 8) nz[tid] = 0;
    __syncthreads();

    for (int i = tid; i < 8 * 128; i += 384) {
        int r = i >> 7, n = i & 127;
        int m = r0 + r;
        float v = tanh_f(g_acc[(size_t)m * 128 + n]);
        xs[r][n] = v;
        if (v != 0.f) nz[r] = 1;
    }
    __syncthreads();

    if (r0 < ROWS_X) {
        unsigned long long acc[8];
        #pragma unroll
        for (int r = 0; r < 8; r++) acc[r] = 0ULL;
        const float* wrow = g_gkT + (size_t)tid * 128;
        #pragma unroll 4
        for (int kb = 0; kb < 128; kb += 4) {
            ulonglong2 w = *(const ulonglong2*)(wrow + kb);
            #pragma unroll
            for (int r = 0; r < 8; r++) {
                ulonglong2 xv = *(const ulonglong2*)&xs[r][kb];
                asm("fma.rn.f32x2 %0, %1, %2, %0;" : "+l"(acc[r]) : "l"(xv.x), "l"(w.x));
                asm("fma.rn.f32x2 %0, %1, %2, %0;" : "+l"(acc[r]) : "l"(xv.y), "l"(w.y));
            }
        }
        const float bias = gbi[tid];
        #pragma unroll
        for (int r = 0; r < 8; r++) {
            float lo, hi;
            asm("mov.b64 {%0, %1}, %2;" : "=f"(lo), "=f"(hi) : "l"(acc[r]));
            g_P[(size_t)(r0 + r) * 384 + tid] = lo + hi + bias;
        }
        if (tid < 8) g_mask[r0 + tid] = nz[tid] ? 1.f : 0.f;
    } else {
        for (int i = tid; i < 8 * 128; i += 384) {
            int r = i >> 7, n = i & 127;
            g_ae[(r0 - ROWS_X + r) * 128 + n] = xs[r][n];
        }
    }
}

// ---------------------------------------------------------------------------
// Kernel 3 (frozen): 32 CTAs x 384 threads; full-K register dot.
// ---------------------------------------------------------------------------
__global__ void __launch_bounds__(384, 1) k3_gru(
    const float* __restrict__ grk, const float* __restrict__ gbr,
    const float* __restrict__ dvec, const float* __restrict__ W1,
    const float* __restrict__ b1, const float* __restrict__ W2,
    const float* __restrict__ b2, float* __restrict__ out)
{
    extern __shared__ float sm3[];
    float* xp  = sm3 + K3_XP;
    float* rp  = sm3 + K3_RP;
    float* h_s = sm3 + K3_H;
    float* msk = sm3 + K3_MSK;
    float* cs  = sm3 + K3_CS;

    const int tid = threadIdx.x;
    const int b = blockIdx.x;
    const bool is_gate = (tid < 128);

    {
        const float* src = g_P + (size_t)b * T_ * 384;
        #pragma unroll
        for (int it = 0; it < 25; it++) {
            int i = it * 1536 + tid * 4;
            cpa16(su32(xp + i), src + i);
        }
        if (tid < 25) cpa16(su32(msk + tid * 4), g_mask + b * T_ + tid * 4);
        asm volatile("cp.async.commit_group;");
    }

    unsigned long long w2[64];
    #pragma unroll
    for (int q = 0; q < 64; q++) {
        float w0 = grk[(2 * q)     * 384 + tid];
        float w1 = grk[(2 * q + 1) * 384 + tid];
        asm("mov.b64 %0, {%1, %2};" : "=l"(w2[q]) : "f"(w0), "f"(w1));
    }
    const float bias = gbr[tid];

    if (is_gate) h_s[tid] = 0.f;
    asm volatile("cp.async.wait_group 0;" ::: "memory");
    __syncthreads();

    for (int t = 0; t < T_; t++) {
        unsigned long long a0 = 0ULL, a1 = 0ULL, a2 = 0ULL, a3 = 0ULL;
        #pragma unroll
        for (int q = 0; q < 8; q++) {
            ulonglong2 u0 = *(const ulonglong2*)&h_s[q * 4];
            ulonglong2 u1 = *(const ulonglong2*)&h_s[32 + q * 4];
            ulonglong2 u2 = *(const ulonglong2*)&h_s[64 + q * 4];
            ulonglong2 u3 = *(const ulonglong2*)&h_s[96 + q * 4];
            asm("fma.rn.f32x2 %0, %1, %2, %0;" : "+l"(a0) : "l"(u0.x), "l"(w2[2 * q]));
            asm("fma.rn.f32x2 %0, %1, %2, %0;" : "+l"(a1) : "l"(u1.x), "l"(w2[16 + 2 * q]));
            asm("fma.rn.f32x2 %0, %1, %2, %0;" : "+l"(a2) : "l"(u2.x), "l"(w2[32 + 2 * q]));
            asm("fma.rn.f32x2 %0, %1, %2, %0;" : "+l"(a3) : "l"(u3.x), "l"(w2[48 + 2 * q]));
            asm("fma.rn.f32x2 %0, %1, %2, %0;" : "+l"(a0) : "l"(u0.y), "l"(w2[2 * q + 1]));
            asm("fma.rn.f32x2 %0, %1, %2, %0;" : "+l"(a1) : "l"(u1.y), "l"(w2[16 + 2 * q + 1]));
            asm("fma.rn.f32x2 %0, %1, %2, %0;" : "+l"(a2) : "l"(u2.y), "l"(w2[32 + 2 * q + 1]));
            asm("fma.rn.f32x2 %0, %1, %2, %0;" : "+l"(a3) : "l"(u3.y), "l"(w2[48 + 2 * q + 1]));
        }
        float s0, s1, s2, s3, s4, s5, s6, s7;
        asm("mov.b64 {%0, %1}, %2;" : "=f"(s0), "=f"(s1) : "l"(a0));
        asm("mov.b64 {%0, %1}, %2;" : "=f"(s2), "=f"(s3) : "l"(a1));
        asm("mov.b64 {%0, %1}, %2;" : "=f"(s4), "=f"(s5) : "l"(a2));
        asm("mov.b64 {%0, %1}, %2;" : "=f"(s6), "=f"(s7) : "l"(a3));
        float dot = ((s0 + s1) + (s2 + s3)) + ((s4 + s5) + (s6 + s7)) + bias;

        float rz = 0.f, xz = 0.f, xr = 0.f, xh = 0.f, m_t = 0.f, hprev = 0.f;
        if (is_gate) {
            rz = dot;
            const float* xpc = xp + t * 384;
            xz = xpc[tid];
            xr = xpc[tid + 128];
            xh = xpc[tid + 256];
            m_t = msk[t];
            hprev = h_s[tid];
        } else {
            rp[tid] = dot;
        }
        __syncthreads();

        if (is_gate) {
            float rr = rp[tid + 128];
            float rh = rp[tid + 256];
            float z  = sigmoid_f(xz + rz);
            float r  = sigmoid_f(xr + rr);
            float hh = tanh_f(xh + r * rh);
            float hn = fmaf(z, hprev - hh, hh);
            h_s[tid] = (m_t != 0.f) ? hn : hprev;
        }
        __syncthreads();
    }

    if (tid < 64) {
        float acc = b1[tid];
        const float* ae = g_ae + b * 128;
        #pragma unroll 4
        for (int k = 0; k < 128; k++) acc = fmaf(h_s[k], W1[k * 64 + tid], acc);
        #pragma unroll 4
        for (int k = 0; k < 128; k++) acc = fmaf(ae[k], W1[(128 + k) * 64 + tid], acc);
        cs[tid] = tanh_f(acc) * W2[tid];
    }
    __syncthreads();
    if (tid == 0) {
        float s = 0.f;
        #pragma unroll 8
        for (int i = 0; i < 64; i++) s += cs[i];
        s += dvec[b * 2] * W2[64] + dvec[b * 2 + 1] * W2[65] + b2[0];
        out[b] = sigmoid_f(s);
    }
}

// ---------------------------------------------------------------------------
extern "C" void kernel_launch(void* const* d_in, const int* in_sizes, int n_in,
                              void* d_out, int out_size)
{
    const float* x   = (const float*)d_in[0];
    const float* a   = (const float*)d_in[1];
    const float* dv  = (const float*)d_in[2];
    const float* emb = (const float*)d_in[3];
    const float* gk  = (const float*)d_in[4];
    const float* grk = (const float*)d_in[5];
    const float* gbi = (const float*)d_in[6];
    const float* gbr = (const float*)d_in[7];
    const float* W1  = (const float*)d_in[8];
    const float* b1  = (const float*)d_in[9];
    const float* W2  = (const float*)d_in[10];
    const float* b2  = (const float*)d_in[11];
    float* out = (float*)d_out;

    cudaFuncSetAttribute(k1_gemm, cudaFuncAttributeMaxDynamicSharedMemorySize, SMEM_K1);
    cudaFuncSetAttribute(k3_gru,  cudaFuncAttributeMaxDynamicSharedMemorySize, SMEM_K3);

    kz_zero<<<404, 256>>>();
    k0_prep<<<NCH, 256>>>(emb);
    k0b_gkT<<<384, 128>>>(gk);
    k1_gemm<<<GRID1, 256, SMEM_K1>>>(x, a);
    k2_reduce_proj<<<ROWS_TOT / 8, 384>>>(gbi);
    k3_gru<<<B_, 384, SMEM_K3>>>(grk, gbr, dv, W1, b1, W2, b2, out);
}

// round 17
// speedup vs baseline: 1.2298x; 1.2298x over previous
#include <cuda_runtime.h>
#include <cstdint>

// ------------------------- problem dims -------------------------
#define B_ 32
#define T_ 100
#define V_ 20000
#define E_ 128
#define H_ 128
#define M_ 64
#define ROWS_X (B_*T_)          // 3200
#define ROWS_TOT (ROWS_X + B_)  // 3232

// ------------------------- k1 config ----------------------------
#define CK 64                   // k per chunk (64 fp16 = 128B rows, SW128)
#define NCH 313                 // ceil(20000/64)
#define NRT 26                  // row tiles of 128
#define NSPL 17                 // K splits
#define BASECH 18               // 313 = 7*19 + 10*18
#define EXTRA 7
#define GRID1 (NRT*NSPL)        // 442

// per-stage smem: AH 16K | BH 16K = 32KB; 3 stages = 96KB
#define STG_BYTES 32768
#define OFF_AH 0
#define OFF_BH 16384
#define SMEM_K1 (3*STG_BYTES)

// k3 dynamic smem layout (floats)
#define K3_XP   0                    // [100*384]
#define K3_RP   (K3_XP + T_*384)     // [384] (only 128..383 used)
#define K3_H    (K3_RP + 384)        // [128]
#define K3_MSK  (K3_H + 128)         // [100]
#define K3_CS   (K3_MSK + 100)       // [64]
#define K3_BAL  (K3_CS + 64)         // [4] ballot words
#define SMEM_K3 ((K3_BAL + 4 + 4) * 4)   // ~156.5 KB

// ------------------------- scratch globals ----------------------
__device__ float    g_acc[(size_t)ROWS_TOT * 128];   // 1.65 MB, L2-resident
__device__ uint32_t g_ebh[(size_t)NCH * 4096];       // emb fp16, tile-swizzled
__device__ float    g_gkT[384 * 128];                // gru_k transposed [j][k]
__device__ float    g_P[(size_t)ROWS_X * 384];
__device__ float    g_mask[ROWS_X];
__device__ float    g_ae[B_ * E_];

// ------------------------- helpers ------------------------------
__device__ __forceinline__ unsigned su32(const void* p) {
    return (unsigned)__cvta_generic_to_shared(p);
}
__device__ __forceinline__ void cpa16(unsigned dst, const void* src) {
    asm volatile("cp.async.ca.shared.global [%0], [%1], 16;\n"
                 :: "r"(dst), "l"(src));
}
__device__ __forceinline__ void ldsm4(uint32_t* r, uint32_t addr) {
    asm volatile("ldmatrix.sync.aligned.m8n8.x4.shared.b16 {%0,%1,%2,%3}, [%4];"
                 : "=r"(r[0]), "=r"(r[1]), "=r"(r[2]), "=r"(r[3]) : "r"(addr));
}
__device__ __forceinline__ void mma16816(float* c, const uint32_t* a, const uint32_t* b) {
    asm volatile("mma.sync.aligned.m16n8k16.row.col.f32.f16.f16.f32 "
                 "{%0,%1,%2,%3}, {%4,%5,%6,%7}, {%8,%9}, {%0,%1,%2,%3};"
                 : "+f"(c[0]), "+f"(c[1]), "+f"(c[2]), "+f"(c[3])
                 : "r"(a[0]), "r"(a[1]), "r"(a[2]), "r"(a[3]), "r"(b[0]), "r"(b[1]));
}
// pack two floats -> fp16x2
__device__ __forceinline__ void cvt2h(float a, float b, uint32_t& p) {
    asm("cvt.rn.f16x2.f32 %0, %1, %2;" : "=r"(p) : "f"(b), "f"(a));
}
__device__ __forceinline__ void redadd(float* p, float v) {
    asm volatile("red.global.add.f32 [%0], %1;" :: "l"(p), "f"(v) : "memory");
}

// fast transcendentals (MUFU-based, err ~2^-22)
#define LOG2E_ 1.4426950408889634f
__device__ __forceinline__ float ex2f(float x) {
    float r; asm("ex2.approx.f32 %0, %1;" : "=f"(r) : "f"(x)); return r;
}
__device__ __forceinline__ float rcpf(float x) {
    float r; asm("rcp.approx.f32 %0, %1;" : "=f"(r) : "f"(x)); return r;
}
__device__ __forceinline__ float sigmoid_f(float v) {
    return rcpf(1.f + ex2f(-v * LOG2E_));
}
__device__ __forceinline__ float tanh_f(float v) {
    return 1.f - 2.f * rcpf(ex2f(2.f * LOG2E_ * v) + 1.f);
}

// ---------------------------------------------------------------------------
// Kernel z: zero the accumulator.
// ---------------------------------------------------------------------------
__global__ void __launch_bounds__(256) kz_zero()
{
    int i = blockIdx.x * 256 + threadIdx.x;
    reinterpret_cast<float4*>(g_acc)[i] = make_float4(0.f, 0.f, 0.f, 0.f);
}

// ---------------------------------------------------------------------------
// Kernel 0: emb -> transposed fp16, SW128-swizzled 16KB tiles.
// ---------------------------------------------------------------------------
__global__ void __launch_bounds__(256) k0_prep(const float* __restrict__ emb)
{
    __shared__ float se[64][129];   // [kl][n]
    const int c = blockIdx.x, tid = threadIdx.x;

    for (int i = tid; i < 64 * 128; i += 256) {
        int kl = i >> 7, r = i & 127;
        int k = c * CK + kl;
        se[kl][r] = (k < V_) ? emb[(size_t)k * E_ + r] : 0.f;
    }
    __syncthreads();

    uint32_t* oh = g_ebh + (size_t)c * 4096;
    for (int p = tid; p < 4096; p += 256) {
        uint32_t bo = p * 4;
        uint32_t lg = bo ^ ((bo >> 3) & 0x70);   // swizzle is an involution
        int r = lg >> 7, kl0 = (lg & 127) >> 1;
        uint32_t hw;
        cvt2h(se[kl0][r], se[kl0 + 1][r], hw);
        oh[p] = hw;
    }
}

// ---------------------------------------------------------------------------
// Kernel 0b: transpose gru_k -> gkT[j][k].
// ---------------------------------------------------------------------------
__global__ void __launch_bounds__(128) k0b_gkT(const float* __restrict__ gk)
{
    const int j = blockIdx.x;       // 0..383
    const int k = threadIdx.x;      // 0..127
    g_gkT[j * 128 + k] = gk[k * 384 + j];
}

// ---------------------------------------------------------------------------
// Kernel 1 (R15 frozen): 1-term fp16 GEMM via ldmatrix + mma.sync (HMMA).
// 512 threads, 16 warps 4x4, warp tile 32x32, CTA tile 128x128.
// 3-stage pipeline, wait_group 1; atomic split-K reduction into g_acc.
// ---------------------------------------------------------------------------
__global__ void __launch_bounds__(512, 1) k1_gemm(
    const float* __restrict__ x, const float* __restrict__ a_)
{
    extern __shared__ char smem[];
    const uint32_t sb = su32(smem);
    const int tid = threadIdx.x;
    const int lane = tid & 31;
    const int wid = tid >> 5;
    const int wm = wid >> 2;
    const int wn = wid & 3;

    const int rt = blockIdx.x % NRT;
    const int sp = blockIdx.x / NRT;
    const int m0 = rt * 128;
    const int nch = BASECH + (sp < EXTRA ? 1 : 0);
    const int c0  = sp * BASECH + (sp < EXTRA ? sp : EXTRA);

    const int arow = tid >> 2;          // 0..127
    const int acol4 = tid & 3;
    const uint32_t xs_a = (uint32_t)(arow & 7) << 4;

    const float* rowp;
    {
        int m = m0 + arow;
        if (m < ROWS_X)        rowp = x  + (size_t)m * V_;
        else if (m < ROWS_TOT) rowp = a_ + (size_t)(m - ROWS_X) * V_;
        else                   rowp = nullptr;
    }

    const int aq = lane >> 3;
    const int a_row_off = (aq & 1) * 8 + (lane & 7);
    const uint32_t a_kboff = (uint32_t)(aq >> 1) * 16;
    const uint32_t abase0 = (uint32_t)(wm * 32 + 0 * 16 + a_row_off) * 128;
    const uint32_t abase1 = (uint32_t)(wm * 32 + 1 * 16 + a_row_off) * 128;
    const int bjj = lane >> 4;
    const uint32_t b_kboff = (uint32_t)((lane >> 3) & 1) * 16;
    const uint32_t bbase0 = (uint32_t)(wn * 32 + 0 * 16 + bjj * 8 + (lane & 7)) * 128;
    const uint32_t bbase1 = (uint32_t)(wn * 32 + 1 * 16 + bjj * 8 + (lane & 7)) * 128;
    const uint32_t xorv = (uint32_t)(lane & 7) << 4;

    float acc[2][4][4];
    #pragma unroll
    for (int i = 0; i < 2; i++)
        #pragma unroll
        for (int j = 0; j < 4; j++)
            #pragma unroll
            for (int q = 0; q < 4; q++) acc[i][j][q] = 0.f;

    float4 av[4];

    auto loadA = [&](int c) {
        #pragma unroll
        for (int q = 0; q < 4; q++) {
            int kb = c * CK + q * 16 + acol4 * 4;
            av[q] = (rowp && kb < V_) ? *(const float4*)(rowp + kb)
                                      : make_float4(0.f, 0.f, 0.f, 0.f);
        }
    };
    auto stsA = [&](int s) {
        const uint32_t ah = sb + s * STG_BYTES + OFF_AH + arow * 128;
        #pragma unroll
        for (int q = 0; q < 4; q++) {
            uint32_t ina = ((uint32_t)(q * 32 + acol4 * 8)) ^ xs_a;
            float4 v = av[q];
            uint32_t h0, h1;
            cvt2h(v.x, v.y, h0);
            cvt2h(v.z, v.w, h1);
            asm volatile("st.shared.v2.b32 [%0], {%1,%2};" :: "r"(ah + ina), "r"(h0), "r"(h1));
        }
    };
    auto cpB = [&](int c, int s) {
        const char* srcH = (const char*)g_ebh + (size_t)c * 16384;
        const uint32_t bh = sb + s * STG_BYTES + OFF_BH;
        #pragma unroll
        for (int j = 0; j < 2; j++) {
            int off = (j * 512 + tid) * 16;
            cpa16(bh + off, srcH + off);
        }
        asm volatile("cp.async.commit_group;");
    };

    auto mmaStep = [&](int s, int ks) {
        const uint32_t ahs = sb + s * STG_BYTES + OFF_AH;
        const uint32_t bhs = sb + s * STG_BYTES + OFF_BH;
        const uint32_t kta = ((uint32_t)(ks * 32) + a_kboff) ^ xorv;
        const uint32_t ktb = ((uint32_t)(ks * 32) + b_kboff) ^ xorv;
        uint32_t ah0[4], ah1[4], bh[2][4];
        ldsm4(ah0, ahs + abase0 + kta);
        ldsm4(ah1, ahs + abase1 + kta);
        ldsm4(bh[0], bhs + bbase0 + ktb);
        ldsm4(bh[1], bhs + bbase1 + ktb);
        #pragma unroll
        for (int j = 0; j < 4; j++) {
            const uint32_t* bhp = &bh[j >> 1][(j & 1) * 2];
            mma16816(acc[0][j], ah0, bhp);
            mma16816(acc[1][j], ah1, bhp);
        }
    };

    // ---- prologue ----
    loadA(c0);
    stsA(0);
    cpB(c0, 0);
    if (nch > 1) { loadA(c0 + 1); cpB(c0 + 1, 1); }

    for (int t = 0; t < nch; t++) {
        const int s = t % 3;
        if (t >= nch - 2) {
            asm volatile("cp.async.wait_group 0;" ::: "memory");
        } else {
            asm volatile("cp.async.wait_group 1;" ::: "memory");
        }
        __syncthreads();

        if (t + 1 < nch) stsA((t + 1) % 3);
        mmaStep(s, 0);
        mmaStep(s, 1);
        if (t + 2 < nch) loadA(c0 + t + 2);
        mmaStep(s, 2);
        mmaStep(s, 3);
        if (t + 2 < nch) cpB(c0 + t + 2, (t + 2) % 3);
    }

    // ---- epilogue: atomically accumulate this split's tile ----
    const int gid = lane >> 2, tig = lane & 3;
    #pragma unroll
    for (int i = 0; i < 2; i++) {
        int mrow = m0 + wm * 32 + i * 16 + gid;
        #pragma unroll
        for (int j = 0; j < 4; j++) {
            int n = wn * 32 + j * 8 + tig * 2;
            if (mrow < ROWS_TOT) {
                float* d0 = g_acc + (size_t)mrow * 128 + n;
                redadd(d0,     acc[i][j][0]);
                redadd(d0 + 1, acc[i][j][1]);
            }
            if (mrow + 8 < ROWS_TOT) {
                float* d1 = g_acc + (size_t)(mrow + 8) * 128 + n;
                redadd(d1,     acc[i][j][2]);
                redadd(d1 + 1, acc[i][j][3]);
            }
        }
    }
}

// ---------------------------------------------------------------------------
// Kernel 2: tanh(g_acc) -> xe; mask; x_proj = xe@gkT + b_i.
// ---------------------------------------------------------------------------
__global__ void __launch_bounds__(384) k2_reduce_proj(const float* __restrict__ gbi)
{
    __shared__ float xs[8][128];
    __shared__ int nz[8];
    const int tid = threadIdx.x;
    const int r0 = blockIdx.x * 8;

    if (tid < 8) nz[tid] = 0;
    __syncthreads();

    for (int i = tid; i < 8 * 128; i += 384) {
        int r = i >> 7, n = i & 127;
        int m = r0 + r;
        float v = tanh_f(g_acc[(size_t)m * 128 + n]);
        xs[r][n] = v;
        if (v != 0.f) nz[r] = 1;
    }
    __syncthreads();

    if (r0 < ROWS_X) {
        unsigned long long acc[8];
        #pragma unroll
        for (int r = 0; r < 8; r++) acc[r] = 0ULL;
        const float* wrow = g_gkT + (size_t)tid * 128;
        #pragma unroll 4
        for (int kb = 0; kb < 128; kb += 4) {
            ulonglong2 w = *(const ulonglong2*)(wrow + kb);
            #pragma unroll
            for (int r = 0; r < 8; r++) {
                ulonglong2 xv = *(const ulonglong2*)&xs[r][kb];
                asm("fma.rn.f32x2 %0, %1, %2, %0;" : "+l"(acc[r]) : "l"(xv.x), "l"(w.x));
                asm("fma.rn.f32x2 %0, %1, %2, %0;" : "+l"(acc[r]) : "l"(xv.y), "l"(w.y));
            }
        }
        const float bias = gbi[tid];
        #pragma unroll
        for (int r = 0; r < 8; r++) {
            float lo, hi;
            asm("mov.b64 {%0, %1}, %2;" : "=f"(lo), "=f"(hi) : "l"(acc[r]));
            g_P[(size_t)(r0 + r) * 384 + tid] = lo + hi + bias;
        }
        if (tid < 8) g_mask[r0 + tid] = nz[tid] ? 1.f : 0.f;
    } else {
        for (int i = tid; i < 8 * 128; i += 384) {
            int r = i >> 7, n = i & 127;
            g_ae[(r0 - ROWS_X + r) * 128 + n] = xs[r][n];
        }
    }
}

// ---------------------------------------------------------------------------
// Kernel 3: 32 CTAs x 384 threads; full-K register dot; gate keeps rz
// in-register. NEW: per-batch effective length via mask ballots — the
// recurrence runs only len steps (mask=0 tail steps are exact no-ops).
// ---------------------------------------------------------------------------
__global__ void __launch_bounds__(384, 1) k3_gru(
    const float* __restrict__ grk, const float* __restrict__ gbr,
    const float* __restrict__ dvec, const float* __restrict__ W1,
    const float* __restrict__ b1, const float* __restrict__ W2,
    const float* __restrict__ b2, float* __restrict__ out)
{
    extern __shared__ float sm3[];
    float* xp  = sm3 + K3_XP;
    float* rp  = sm3 + K3_RP;
    float* h_s = sm3 + K3_H;
    float* msk = sm3 + K3_MSK;
    float* cs  = sm3 + K3_CS;
    int*   bal = (int*)(sm3 + K3_BAL);

    const int tid = threadIdx.x;
    const int b = blockIdx.x;
    const bool is_gate = (tid < 128);

    {
        const float* src = g_P + (size_t)b * T_ * 384;
        #pragma unroll
        for (int it = 0; it < 25; it++) {
            int i = it * 1536 + tid * 4;
            cpa16(su32(xp + i), src + i);
        }
        if (tid < 25) cpa16(su32(msk + tid * 4), g_mask + b * T_ + tid * 4);
        asm volatile("cp.async.commit_group;");
    }

    unsigned long long w2[64];
    #pragma unroll
    for (int q = 0; q < 64; q++) {
        float w0 = grk[(2 * q)     * 384 + tid];
        float w1 = grk[(2 * q + 1) * 384 + tid];
        asm("mov.b64 %0, {%1, %2};" : "=l"(w2[q]) : "f"(w0), "f"(w1));
    }
    const float bias = gbr[tid];

    if (is_gate) h_s[tid] = 0.f;
    asm volatile("cp.async.wait_group 0;" ::: "memory");
    __syncthreads();

    // effective length: highest t with msk[t] != 0, +1  (4 warp ballots)
    if (tid < 128) {
        int p = (tid < T_) && (msk[tid] != 0.f);
        unsigned m = __ballot_sync(0xFFFFFFFFu, p);
        if ((tid & 31) == 0) bal[tid >> 5] = (int)m;
    }
    __syncthreads();
    int len = 0;
    {
        #pragma unroll
        for (int w = 3; w >= 0; w--) {
            unsigned m = (unsigned)bal[w];
            if (m) { len = w * 32 + (31 - __clz(m)) + 1; break; }
        }
    }

    for (int t = 0; t < len; t++) {
        unsigned long long a0 = 0ULL, a1 = 0ULL, a2 = 0ULL, a3 = 0ULL;
        #pragma unroll
        for (int q = 0; q < 8; q++) {
            ulonglong2 u0 = *(const ulonglong2*)&h_s[q * 4];
            ulonglong2 u1 = *(const ulonglong2*)&h_s[32 + q * 4];
            ulonglong2 u2 = *(const ulonglong2*)&h_s[64 + q * 4];
            ulonglong2 u3 = *(const ulonglong2*)&h_s[96 + q * 4];
            asm("fma.rn.f32x2 %0, %1, %2, %0;" : "+l"(a0) : "l"(u0.x), "l"(w2[2 * q]));
            asm("fma.rn.f32x2 %0, %1, %2, %0;" : "+l"(a1) : "l"(u1.x), "l"(w2[16 + 2 * q]));
            asm("fma.rn.f32x2 %0, %1, %2, %0;" : "+l"(a2) : "l"(u2.x), "l"(w2[32 + 2 * q]));
            asm("fma.rn.f32x2 %0, %1, %2, %0;" : "+l"(a3) : "l"(u3.x), "l"(w2[48 + 2 * q]));
            asm("fma.rn.f32x2 %0, %1, %2, %0;" : "+l"(a0) : "l"(u0.y), "l"(w2[2 * q + 1]));
            asm("fma.rn.f32x2 %0, %1, %2, %0;" : "+l"(a1) : "l"(u1.y), "l"(w2[16 + 2 * q + 1]));
            asm("fma.rn.f32x2 %0, %1, %2, %0;" : "+l"(a2) : "l"(u2.y), "l"(w2[32 + 2 * q + 1]));
            asm("fma.rn.f32x2 %0, %1, %2, %0;" : "+l"(a3) : "l"(u3.y), "l"(w2[48 + 2 * q + 1]));
        }
        float s0, s1, s2, s3, s4, s5, s6, s7;
        asm("mov.b64 {%0, %1}, %2;" : "=f"(s0), "=f"(s1) : "l"(a0));
        asm("mov.b64 {%0, %1}, %2;" : "=f"(s2), "=f"(s3) : "l"(a1));
        asm("mov.b64 {%0, %1}, %2;" : "=f"(s4), "=f"(s5) : "l"(a2));
        asm("mov.b64 {%0, %1}, %2;" : "=f"(s6), "=f"(s7) : "l"(a3));
        float dot = ((s0 + s1) + (s2 + s3)) + ((s4 + s5) + (s6 + s7)) + bias;

        float rz = 0.f, xz = 0.f, xr = 0.f, xh = 0.f, m_t = 0.f, hprev = 0.f;
        if (is_gate) {
            rz = dot;
            const float* xpc = xp + t * 384;
            xz = xpc[tid];
            xr = xpc[tid + 128];
            xh = xpc[tid + 256];
            m_t = msk[t];
            hprev = h_s[tid];
        } else {
            rp[tid] = dot;
        }
        __syncthreads();

        if (is_gate) {
            float rr = rp[tid + 128];
            float rh = rp[tid + 256];
            float z  = sigmoid_f(xz + rz);
            float r  = sigmoid_f(xr + rr);
            float hh = tanh_f(xh + r * rh);
            float hn = fmaf(z, hprev - hh, hh);
            h_s[tid] = (m_t != 0.f) ? hn : hprev;
        }
        __syncthreads();
    }

    if (tid < 64) {
        float acc = b1[tid];
        const float* ae = g_ae + b * 128;
        #pragma unroll 4
        for (int k = 0; k < 128; k++) acc = fmaf(h_s[k], W1[k * 64 + tid], acc);
        #pragma unroll 4
        for (int k = 0; k < 128; k++) acc = fmaf(ae[k], W1[(128 + k) * 64 + tid], acc);
        cs[tid] = tanh_f(acc) * W2[tid];
    }
    __syncthreads();
    if (tid == 0) {
        float s = 0.f;
        #pragma unroll 8
        for (int i = 0; i < 64; i++) s += cs[i];
        s += dvec[b * 2] * W2[64] + dvec[b * 2 + 1] * W2[65] + b2[0];
        out[b] = sigmoid_f(s);
    }
}

// ---------------------------------------------------------------------------
extern "C" void kernel_launch(void* const* d_in, const int* in_sizes, int n_in,
                              void* d_out, int out_size)
{
    const float* x   = (const float*)d_in[0];
    const float* a   = (const float*)d_in[1];
    const float* dv  = (const float*)d_in[2];
    const float* emb = (const float*)d_in[3];
    const float* gk  = (const float*)d_in[4];
    const float* grk = (const float*)d_in[5];
    const float* gbi = (const float*)d_in[6];
    const float* gbr = (const float*)d_in[7];
    const float* W1  = (const float*)d_in[8];
    const float* b1  = (const float*)d_in[9];
    const float* W2  = (const float*)d_in[10];
    const float* b2  = (const float*)d_in[11];
    float* out = (float*)d_out;

    cudaFuncSetAttribute(k1_gemm, cudaFuncAttributeMaxDynamicSharedMemorySize, SMEM_K1);
    cudaFuncSetAttribute(k3_gru,  cudaFuncAttributeMaxDynamicSharedMemorySize, SMEM_K3);

    kz_zero<<<404, 256>>>();
    k0_prep<<<NCH, 256>>>(emb);
    k0b_gkT<<<384, 128>>>(gk);
    k1_gemm<<<GRID1, 512, SMEM_K1>>>(x, a);
    k2_reduce_proj<<<ROWS_TOT / 8, 384>>>(gbi);
    k3_gru<<<B_, 384, SMEM_K3>>>(grk, gbr, dv, W1, b1, W2, b2, out);
}